// round 12
// baseline (speedup 1.0000x reference)
#include <cuda_runtime.h>
#include <cuda_bf16.h>
#include <stdint.h>
#include <math.h>

#define B_ 64
#define W_ 256
#define N_ 128
#define L_ 64
#define WC 64                      // windows per CTA (4 CTAs per batch)
#define THREADS 256
#define PADK 72                    // bf16 row stride: 144B -> conflict-free ldmatrix

// smem byte offsets
#define OFF_AHI 0                  // [64][PADK] bf16
#define OFF_ALO 9216
#define OFF_BHI 18432              // [128][PADK] bf16
#define OFF_BLO 36864
#define OFF_SXX 55296              // [64]  f32 window norms
#define OFF_SSN 55552              // [128] f32 shapelet norms
#define OFF_UMIN 56064             // [128] u32 min d^2 bits
#define OFF_RED 56576              // [4] f32
#define OFF_TKT 56592              // [1] int
#define SMEM_TOTAL 56640

__device__ float g_part[B_][4][N_];
__device__ int   g_cnt[B_];

__device__ __forceinline__ uint32_t smem_u32(const void* p) {
    uint32_t a;
    asm("{ .reg .u64 t; cvta.to.shared.u64 t, %1; cvt.u32.u64 %0, t; }" : "=r"(a) : "l"(p));
    return a;
}

#define LDSM_X4(r, addr) \
    asm volatile("ldmatrix.sync.aligned.m8n8.x4.shared.b16 {%0,%1,%2,%3}, [%4];" \
                 : "=r"((r)[0]), "=r"((r)[1]), "=r"((r)[2]), "=r"((r)[3]) : "r"(addr))

#define MMA_BF16(c, a, b0, b1) \
    asm volatile("mma.sync.aligned.m16n8k16.row.col.f32.bf16.bf16.f32 " \
                 "{%0,%1,%2,%3},{%4,%5,%6,%7},{%8,%9},{%0,%1,%2,%3};" \
                 : "+f"((c)[0]), "+f"((c)[1]), "+f"((c)[2]), "+f"((c)[3]) \
                 : "r"((a)[0]), "r"((a)[1]), "r"((a)[2]), "r"((a)[3]), "r"(b0), "r"(b1))

__global__ void __launch_bounds__(THREADS, 2) fused_kernel(const float* __restrict__ x,
                                                           const float* __restrict__ sh,
                                                           const float* __restrict__ cw,
                                                           const float* __restrict__ cb,
                                                           float* __restrict__ out) {
    extern __shared__ char sm[];
    const uint32_t smb = smem_u32(sm);
    const int tid  = threadIdx.x;
    const int wid  = tid >> 5, lane = tid & 31;
    const int b    = blockIdx.x >> 2, quarter = blockIdx.x & 3;

    float* sxx = (float*)(sm + OFF_SXX);
    float* ssn = (float*)(sm + OFF_SSN);
    unsigned int* umin = (unsigned int*)(sm + OFF_UMIN);
    float* red = (float*)(sm + OFF_RED);
    int*   tkt = (int*)(sm + OFF_TKT);

    if (tid < N_) umin[tid] = 0x7F800000u;

    // ---- phase 1: coalesced loads (2 rows / warp-instr), packed converts ----
    // 96 row-pairs total: pairs 0-31 = x windows (64 rows), 32-95 = shapelets (128 rows).
    {
        const float* xb = x + (size_t)(b * W_ + quarter * WC) * L_;
        const int ro  = lane >> 4;           // which of the 2 rows
        const int col = (lane & 15) * 4;     // 4 floats per lane

        #pragma unroll
        for (int it = 0; it < 12; it++) {
            const int rp  = wid + it * 8;    // row-pair index 0..95
            const bool isA = rp < 32;
            const int r   = (isA ? rp * 2 : (rp - 32) * 2) + ro;
            const float* src = (isA ? xb : sh) + (size_t)r * L_ + col;
            char* thi = sm + (isA ? OFF_AHI : OFF_BHI);
            char* tlo = sm + (isA ? OFF_ALO : OFF_BLO);

            float4 v = *(const float4*)src;

            __nv_bfloat162 h0 = __float22bfloat162_rn(make_float2(v.x, v.y));
            __nv_bfloat162 h1 = __float22bfloat162_rn(make_float2(v.z, v.w));
            uint32_t u0 = *(uint32_t*)&h0, u1 = *(uint32_t*)&h1;
            float hx = __uint_as_float(u0 << 16), hy = __uint_as_float(u0 & 0xFFFF0000u);
            float hz = __uint_as_float(u1 << 16), hw = __uint_as_float(u1 & 0xFFFF0000u);
            __nv_bfloat162 l0 = __float22bfloat162_rn(make_float2(v.x - hx, v.y - hy));
            __nv_bfloat162 l1 = __float22bfloat162_rn(make_float2(v.z - hz, v.w - hw));

            const uint32_t o = (uint32_t)(r * PADK + col) * 2;
            *(uint2*)(thi + o) = make_uint2(u0, u1);
            uint32_t w0 = *(uint32_t*)&l0, w1 = *(uint32_t*)&l1;
            *(uint2*)(tlo + o) = make_uint2(w0, w1);

            float nr = fmaf(v.x, v.x, fmaf(v.y, v.y, fmaf(v.z, v.z, v.w * v.w)));
            nr += __shfl_xor_sync(0xffffffffu, nr, 1);
            nr += __shfl_xor_sync(0xffffffffu, nr, 2);
            nr += __shfl_xor_sync(0xffffffffu, nr, 4);
            nr += __shfl_xor_sync(0xffffffffu, nr, 8);
            if ((lane & 15) == 0) (isA ? sxx : ssn)[r] = nr;
        }
    }
    __syncthreads();

    // ---- phase 2: 8 warps, warp tile 32(M) x 32(N); per kstep load all frags ----
    const int mbase = (wid & 1) * 32;
    const int nbase = (wid >> 1) * 32;

    float acc[2][4][4];
    #pragma unroll
    for (int mt = 0; mt < 2; mt++)
        #pragma unroll
        for (int j = 0; j < 4; j++)
            #pragma unroll
            for (int e = 0; e < 4; e++) acc[mt][j][e] = 0.f;

    const uint32_t a_off = (uint32_t)((mbase + (lane & 15)) * PADK + (lane >> 4) * 8) * 2;
    const uint32_t q = lane >> 3;
    const uint32_t b_off = (uint32_t)((nbase + ((q >> 1) << 3) + (lane & 7)) * PADK
                                      + (q & 1) * 8) * 2;

    const uint32_t ahB = smb + OFF_AHI + a_off, alB = smb + OFF_ALO + a_off;
    const uint32_t bhB = smb + OFF_BHI + b_off, blB = smb + OFF_BLO + b_off;

    #pragma unroll
    for (int ks = 0; ks < 4; ks++) {
        const uint32_t ko = ks * 32;           // 16 bf16 cols = 32 bytes
        uint32_t Ah[2][4], Al[2][4], Bh[2][4], Bl[2][4];
        LDSM_X4(Ah[0], ahB + ko);
        LDSM_X4(Ah[1], ahB + 16 * PADK * 2 + ko);
        LDSM_X4(Al[0], alB + ko);
        LDSM_X4(Al[1], alB + 16 * PADK * 2 + ko);
        LDSM_X4(Bh[0], bhB + ko);
        LDSM_X4(Bh[1], bhB + 16 * PADK * 2 + ko);
        LDSM_X4(Bl[0], blB + ko);
        LDSM_X4(Bl[1], blB + 16 * PADK * 2 + ko);
        #pragma unroll
        for (int mt = 0; mt < 2; mt++)
            #pragma unroll
            for (int j = 0; j < 4; j++) {
                const int jh = j >> 1, je = (j & 1) * 2;
                MMA_BF16(acc[mt][j], Ah[mt], Bh[jh][je], Bh[jh][je + 1]);  // hi*hi
                MMA_BF16(acc[mt][j], Ah[mt], Bl[jh][je], Bl[jh][je + 1]);  // hi*lo
                MMA_BF16(acc[mt][j], Al[mt], Bh[jh][je], Bh[jh][je + 1]);  // lo*hi
            }
    }

    // ---- epilogue: d^2 = xr + sn - 2*dot; min over the warp's 32 rows ----
    {
        const int g = lane >> 2, t = lane & 3;
        const float xr0 = sxx[mbase + g],      xr1 = sxx[mbase + 8 + g];
        const float xr2 = sxx[mbase + 16 + g], xr3 = sxx[mbase + 24 + g];
        #pragma unroll
        for (int j = 0; j < 4; j++) {
            float v0 = fminf(fminf(fmaf(-2.f, acc[0][j][0], xr0), fmaf(-2.f, acc[0][j][2], xr1)),
                             fminf(fmaf(-2.f, acc[1][j][0], xr2), fmaf(-2.f, acc[1][j][2], xr3)));
            float v1 = fminf(fminf(fmaf(-2.f, acc[0][j][1], xr0), fmaf(-2.f, acc[0][j][3], xr1)),
                             fminf(fmaf(-2.f, acc[1][j][1], xr2), fmaf(-2.f, acc[1][j][3], xr3)));
            #pragma unroll
            for (int o = 4; o <= 16; o <<= 1) {
                v0 = fminf(v0, __shfl_xor_sync(0xffffffffu, v0, o));
                v1 = fminf(v1, __shfl_xor_sync(0xffffffffu, v1, o));
            }
            if (lane < 4) {
                int c0 = nbase + j * 8 + t * 2;
                atomicMin(&umin[c0],     __float_as_uint(fmaxf(v0 + ssn[c0], 0.f)));
                atomicMin(&umin[c0 + 1], __float_as_uint(fmaxf(v1 + ssn[c0 + 1], 0.f)));
            }
        }
    }
    __syncthreads();

    // ---- publish quarter-min, ticket; last of 4 merges + classifies ----
    if (tid < N_) __stcg(&g_part[b][quarter][tid], __uint_as_float(umin[tid]));
    __threadfence();
    __syncthreads();
    if (tid == 0) tkt[0] = atomicAdd(&g_cnt[b], 1);
    __syncthreads();

    if (tkt[0] == 3) {
        __threadfence();
        float v = 0.f;
        if (tid < N_) {
            float d2 = __uint_as_float(umin[tid]);
            #pragma unroll
            for (int qq = 0; qq < 4; qq++)
                if (qq != quarter) d2 = fminf(d2, __ldcg(&g_part[b][qq][tid]));
            v = sqrtf(fmaxf(d2, 0.f)) * cw[tid];
        }
        #pragma unroll
        for (int o = 16; o; o >>= 1) v += __shfl_xor_sync(0xffffffffu, v, o);
        if (tid < N_ && (tid & 31) == 0) red[tid >> 5] = v;
        __syncthreads();
        if (tid == 0) {
            float s = red[0] + red[1] + red[2] + red[3] + cb[0];
            out[b] = 1.f / (1.f + expf(-s));
            atomicExch(&g_cnt[b], 0);          // reset for next graph replay
        }
    }
}

extern "C" void kernel_launch(void* const* d_in, const int* in_sizes, int n_in,
                              void* d_out, int out_size) {
    const float* x  = (const float*)d_in[0];
    const float* sh = (const float*)d_in[1];
    const float* cw = (const float*)d_in[2];
    const float* cb = (const float*)d_in[3];
    float* out = (float*)d_out;

    cudaFuncSetAttribute(fused_kernel, cudaFuncAttributeMaxDynamicSharedMemorySize, SMEM_TOTAL);
    fused_kernel<<<4 * B_, THREADS, SMEM_TOTAL>>>(x, sh, cw, cb, out);
}

// round 14
// speedup vs baseline: 1.0657x; 1.0657x over previous
#include <cuda_runtime.h>
#include <cuda_bf16.h>
#include <stdint.h>
#include <math.h>

#define B_ 64
#define W_ 256
#define N_ 128
#define L_ 64
#define WC 128
#define THREADS 512
#define PADK 72                    // bf16 row stride: 144B -> conflict-free ldmatrix

// smem byte offsets
#define OFF_AHI 0
#define OFF_ALO 18432
#define OFF_BHI 36864
#define OFF_BLO 55296
#define OFF_SXX 73728              // [128] f32 window norms
#define OFF_SSN (73728 + 512)      // [128] f32 shapelet norms
#define OFF_UMIN (73728 + 1024)    // [128] u32 min d^2 bits
#define OFF_RED (73728 + 1536)     // [4] f32
#define OFF_TKT (73728 + 1552)     // [1] int
#define SMEM_TOTAL (73728 + 1600)

__device__ float g_part[B_][2][N_];
__device__ int   g_cnt[B_];

__device__ __forceinline__ uint32_t smem_u32(const void* p) {
    uint32_t a;
    asm("{ .reg .u64 t; cvta.to.shared.u64 t, %1; cvt.u32.u64 %0, t; }" : "=r"(a) : "l"(p));
    return a;
}

#define LDSM_X4(r, addr) \
    asm volatile("ldmatrix.sync.aligned.m8n8.x4.shared.b16 {%0,%1,%2,%3}, [%4];" \
                 : "=r"((r)[0]), "=r"((r)[1]), "=r"((r)[2]), "=r"((r)[3]) : "r"(addr))

#define MMA_BF16(c, a, b0, b1) \
    asm volatile("mma.sync.aligned.m16n8k16.row.col.f32.bf16.bf16.f32 " \
                 "{%0,%1,%2,%3},{%4,%5,%6,%7},{%8,%9},{%0,%1,%2,%3};" \
                 : "+f"((c)[0]), "+f"((c)[1]), "+f"((c)[2]), "+f"((c)[3]) \
                 : "r"((a)[0]), "r"((a)[1]), "r"((a)[2]), "r"((a)[3]), "r"(b0), "r"(b1))

__global__ void __launch_bounds__(THREADS) fused_kernel(const float* __restrict__ x,
                                                        const float* __restrict__ sh,
                                                        const float* __restrict__ cw,
                                                        const float* __restrict__ cb,
                                                        float* __restrict__ out) {
    extern __shared__ char sm[];
    const uint32_t smb = smem_u32(sm);
    const int tid  = threadIdx.x;
    const int wid  = tid >> 5, lane = tid & 31;
    const int b    = blockIdx.x >> 1, half = blockIdx.x & 1;

    float* sxx = (float*)(sm + OFF_SXX);
    float* ssn = (float*)(sm + OFF_SSN);
    unsigned int* umin = (unsigned int*)(sm + OFF_UMIN);
    float* red = (float*)(sm + OFF_RED);
    int*   tkt = (int*)(sm + OFF_TKT);

    if (tid < N_) umin[tid] = 0x7F800000u;

    // ---- phase 1: coalesced (2 rows / warp-instr); batch 4 LDGs then convert ----
    // Warps 0-7: x rows; warps 8-15: shapelet rows. 16 rows per warp.
    {
        const bool isA  = wid < 8;
        const int rbase = (wid & 7) * 16;
        const float* base = isA ? x + (size_t)(b * W_ + half * WC) * L_ : sh;
        char* thi = sm + (isA ? OFF_AHI : OFF_BHI);
        char* tlo = sm + (isA ? OFF_ALO : OFF_BLO);
        float* nrm = isA ? sxx : ssn;
        const int ro  = lane >> 4;           // which of the 2 rows
        const int col = (lane & 15) * 4;     // 4 floats per lane

        #pragma unroll
        for (int hb = 0; hb < 2; hb++) {
            // front-batch 4 independent LDG.128s (MLP=4)
            float4 v[4];
            #pragma unroll
            for (int i = 0; i < 4; i++) {
                const int r = rbase + (hb * 4 + i) * 2 + ro;
                v[i] = *(const float4*)(base + (size_t)r * L_ + col);
            }
            #pragma unroll
            for (int i = 0; i < 4; i++) {
                const int r = rbase + (hb * 4 + i) * 2 + ro;
                __nv_bfloat162 h0 = __float22bfloat162_rn(make_float2(v[i].x, v[i].y));
                __nv_bfloat162 h1 = __float22bfloat162_rn(make_float2(v[i].z, v[i].w));
                uint32_t u0 = *(uint32_t*)&h0, u1 = *(uint32_t*)&h1;
                float hx = __uint_as_float(u0 << 16), hy = __uint_as_float(u0 & 0xFFFF0000u);
                float hz = __uint_as_float(u1 << 16), hw = __uint_as_float(u1 & 0xFFFF0000u);
                __nv_bfloat162 l0 = __float22bfloat162_rn(make_float2(v[i].x - hx, v[i].y - hy));
                __nv_bfloat162 l1 = __float22bfloat162_rn(make_float2(v[i].z - hz, v[i].w - hw));

                const uint32_t o = (uint32_t)(r * PADK + col) * 2;
                *(uint2*)(thi + o) = make_uint2(u0, u1);
                uint32_t w0 = *(uint32_t*)&l0, w1 = *(uint32_t*)&l1;
                *(uint2*)(tlo + o) = make_uint2(w0, w1);

                float nr = fmaf(v[i].x, v[i].x, fmaf(v[i].y, v[i].y,
                           fmaf(v[i].z, v[i].z, v[i].w * v[i].w)));
                nr += __shfl_xor_sync(0xffffffffu, nr, 1);
                nr += __shfl_xor_sync(0xffffffffu, nr, 2);
                nr += __shfl_xor_sync(0xffffffffu, nr, 4);
                nr += __shfl_xor_sync(0xffffffffu, nr, 8);
                if ((lane & 15) == 0) nrm[r] = nr;
            }
        }
    }
    __syncthreads();

    // ---- phase 2: 16 warps, warp tile 32(M) x 32(N); per kstep load all frags ----
    const int mbase = (wid & 3) * 32;
    const int nbase = (wid >> 2) * 32;

    float acc[2][4][4];
    #pragma unroll
    for (int mt = 0; mt < 2; mt++)
        #pragma unroll
        for (int j = 0; j < 4; j++)
            #pragma unroll
            for (int e = 0; e < 4; e++) acc[mt][j][e] = 0.f;

    const uint32_t a_off = (uint32_t)((mbase + (lane & 15)) * PADK + (lane >> 4) * 8) * 2;
    const uint32_t q = lane >> 3;
    const uint32_t b_off = (uint32_t)((nbase + ((q >> 1) << 3) + (lane & 7)) * PADK
                                      + (q & 1) * 8) * 2;

    const uint32_t ahB = smb + OFF_AHI + a_off, alB = smb + OFF_ALO + a_off;
    const uint32_t bhB = smb + OFF_BHI + b_off, blB = smb + OFF_BLO + b_off;

    #pragma unroll
    for (int ks = 0; ks < 4; ks++) {
        const uint32_t ko = ks * 32;           // 16 bf16 cols = 32 bytes
        uint32_t Ah[2][4], Al[2][4], Bh[2][4], Bl[2][4];
        LDSM_X4(Ah[0], ahB + ko);
        LDSM_X4(Ah[1], ahB + 16 * PADK * 2 + ko);
        LDSM_X4(Al[0], alB + ko);
        LDSM_X4(Al[1], alB + 16 * PADK * 2 + ko);
        LDSM_X4(Bh[0], bhB + ko);
        LDSM_X4(Bh[1], bhB + 16 * PADK * 2 + ko);
        LDSM_X4(Bl[0], blB + ko);
        LDSM_X4(Bl[1], blB + 16 * PADK * 2 + ko);
        #pragma unroll
        for (int mt = 0; mt < 2; mt++)
            #pragma unroll
            for (int j = 0; j < 4; j++) {
                const int jh = j >> 1, je = (j & 1) * 2;
                MMA_BF16(acc[mt][j], Ah[mt], Bh[jh][je], Bh[jh][je + 1]);  // hi*hi
                MMA_BF16(acc[mt][j], Ah[mt], Bl[jh][je], Bl[jh][je + 1]);  // hi*lo
                MMA_BF16(acc[mt][j], Al[mt], Bh[jh][je], Bh[jh][je + 1]);  // lo*hi
            }
    }

    // ---- epilogue: d^2 = xr + sn - 2*dot; min over the warp's 32 rows ----
    {
        const int g = lane >> 2, t = lane & 3;
        const float xr0 = sxx[mbase + g],      xr1 = sxx[mbase + 8 + g];
        const float xr2 = sxx[mbase + 16 + g], xr3 = sxx[mbase + 24 + g];
        #pragma unroll
        for (int j = 0; j < 4; j++) {
            float v0 = fminf(fminf(fmaf(-2.f, acc[0][j][0], xr0), fmaf(-2.f, acc[0][j][2], xr1)),
                             fminf(fmaf(-2.f, acc[1][j][0], xr2), fmaf(-2.f, acc[1][j][2], xr3)));
            float v1 = fminf(fminf(fmaf(-2.f, acc[0][j][1], xr0), fmaf(-2.f, acc[0][j][3], xr1)),
                             fminf(fmaf(-2.f, acc[1][j][1], xr2), fmaf(-2.f, acc[1][j][3], xr3)));
            #pragma unroll
            for (int o = 4; o <= 16; o <<= 1) {
                v0 = fminf(v0, __shfl_xor_sync(0xffffffffu, v0, o));
                v1 = fminf(v1, __shfl_xor_sync(0xffffffffu, v1, o));
            }
            if (lane < 4) {
                int c0 = nbase + j * 8 + t * 2;
                atomicMin(&umin[c0],     __float_as_uint(fmaxf(v0 + ssn[c0], 0.f)));
                atomicMin(&umin[c0 + 1], __float_as_uint(fmaxf(v1 + ssn[c0 + 1], 0.f)));
            }
        }
    }
    __syncthreads();

    // ---- publish half-min, ticket; last block of the pair merges + classifies ----
    if (tid < N_) __stcg(&g_part[b][half][tid], __uint_as_float(umin[tid]));
    __threadfence();
    __syncthreads();
    if (tid == 0) tkt[0] = atomicAdd(&g_cnt[b], 1);
    __syncthreads();

    if (tkt[0] == 1) {
        __threadfence();
        float v = 0.f;
        if (tid < N_) {
            float other = __ldcg(&g_part[b][1 - half][tid]);
            float d2 = fminf(__uint_as_float(umin[tid]), other);
            v = sqrtf(fmaxf(d2, 0.f)) * cw[tid];
        }
        #pragma unroll
        for (int o = 16; o; o >>= 1) v += __shfl_xor_sync(0xffffffffu, v, o);
        if (tid < N_ && (tid & 31) == 0) red[tid >> 5] = v;
        __syncthreads();
        if (tid == 0) {
            float s = red[0] + red[1] + red[2] + red[3] + cb[0];
            out[b] = 1.f / (1.f + expf(-s));
            atomicExch(&g_cnt[b], 0);          // reset for next graph replay
        }
    }
}

extern "C" void kernel_launch(void* const* d_in, const int* in_sizes, int n_in,
                              void* d_out, int out_size) {
    const float* x  = (const float*)d_in[0];
    const float* sh = (const float*)d_in[1];
    const float* cw = (const float*)d_in[2];
    const float* cb = (const float*)d_in[3];
    float* out = (float*)d_out;

    cudaFuncSetAttribute(fused_kernel, cudaFuncAttributeMaxDynamicSharedMemorySize, SMEM_TOTAL);
    fused_kernel<<<2 * B_, THREADS, SMEM_TOTAL>>>(x, sh, cw, cb, out);
}

// round 16
// speedup vs baseline: 1.1019x; 1.0340x over previous
#include <cuda_runtime.h>
#include <cuda_bf16.h>
#include <stdint.h>
#include <math.h>

#define B_ 64
#define W_ 256
#define N_ 128
#define L_ 64
#define WC 128
#define THREADS 512
#define PADK 72                    // bf16 row stride: 144B -> conflict-free ldmatrix

// smem byte offsets
#define OFF_AHI 0
#define OFF_ALO 18432
#define OFF_BHI 36864
#define OFF_BLO 55296
#define OFF_SXX 73728              // [128] f32 window norms
#define OFF_SSN (73728 + 512)      // [128] f32 shapelet norms
#define OFF_UMIN (73728 + 1024)    // [128] u32 min d^2 bits
#define OFF_RED  (73728 + 1536)    // [4] f32
#define OFF_PEER (73728 + 1552)    // [128] u32 peer half-min (written via DSMEM)
#define SMEM_TOTAL (73728 + 2064)

__device__ __forceinline__ uint32_t smem_u32(const void* p) {
    uint32_t a;
    asm("{ .reg .u64 t; cvta.to.shared.u64 t, %1; cvt.u32.u64 %0, t; }" : "=r"(a) : "l"(p));
    return a;
}

#define LDSM_X4(r, addr) \
    asm volatile("ldmatrix.sync.aligned.m8n8.x4.shared.b16 {%0,%1,%2,%3}, [%4];" \
                 : "=r"((r)[0]), "=r"((r)[1]), "=r"((r)[2]), "=r"((r)[3]) : "r"(addr))

#define MMA_BF16(c, a, b0, b1) \
    asm volatile("mma.sync.aligned.m16n8k16.row.col.f32.bf16.bf16.f32 " \
                 "{%0,%1,%2,%3},{%4,%5,%6,%7},{%8,%9},{%0,%1,%2,%3};" \
                 : "+f"((c)[0]), "+f"((c)[1]), "+f"((c)[2]), "+f"((c)[3]) \
                 : "r"((a)[0]), "r"((a)[1]), "r"((a)[2]), "r"((a)[3]), "r"(b0), "r"(b1))

// load all 8 fragment quads for one k-step
#define LOAD_FRAGS(F, ko) do {                                   \
    LDSM_X4(F[0], ahB + (ko));                                   \
    LDSM_X4(F[1], ahB + 16 * PADK * 2 + (ko));                   \
    LDSM_X4(F[2], alB + (ko));                                   \
    LDSM_X4(F[3], alB + 16 * PADK * 2 + (ko));                   \
    LDSM_X4(F[4], bhB + (ko));                                   \
    LDSM_X4(F[5], bhB + 16 * PADK * 2 + (ko));                   \
    LDSM_X4(F[6], blB + (ko));                                   \
    LDSM_X4(F[7], blB + 16 * PADK * 2 + (ko));                   \
} while (0)

// F layout: [0]=Ah0 [1]=Ah1 [2]=Al0 [3]=Al1 [4]=Bh0 [5]=Bh1 [6]=Bl0 [7]=Bl1
#define DO_MMAS(F) do {                                                          \
    _Pragma("unroll")                                                            \
    for (int mt = 0; mt < 2; mt++)                                               \
        _Pragma("unroll")                                                        \
        for (int j = 0; j < 4; j++) {                                            \
            const int jh = j >> 1, je = (j & 1) * 2;                             \
            MMA_BF16(acc[mt][j], F[mt],     F[4 + jh][je], F[4 + jh][je + 1]);   \
            MMA_BF16(acc[mt][j], F[mt],     F[6 + jh][je], F[6 + jh][je + 1]);   \
            MMA_BF16(acc[mt][j], F[2 + mt], F[4 + jh][je], F[4 + jh][je + 1]);   \
        }                                                                        \
} while (0)

__global__ void __launch_bounds__(THREADS) __cluster_dims__(2, 1, 1)
fused_kernel(const float* __restrict__ x,
             const float* __restrict__ sh,
             const float* __restrict__ cw,
             const float* __restrict__ cb,
             float* __restrict__ out) {
    extern __shared__ char sm[];
    const uint32_t smb = smem_u32(sm);
    const int tid  = threadIdx.x;
    const int wid  = tid >> 5, lane = tid & 31;
    const int b    = blockIdx.x >> 1, half = blockIdx.x & 1;   // half == cluster rank

    float* sxx = (float*)(sm + OFF_SXX);
    float* ssn = (float*)(sm + OFF_SSN);
    unsigned int* umin = (unsigned int*)(sm + OFF_UMIN);
    float* red = (float*)(sm + OFF_RED);
    unsigned int* peer = (unsigned int*)(sm + OFF_PEER);

    if (tid < N_) umin[tid] = 0x7F800000u;

    // ---- phase 1: coalesced (2 rows / warp-instr); batch 4 LDGs then convert ----
    {
        const bool isA  = wid < 8;
        const int rbase = (wid & 7) * 16;
        const float* base = isA ? x + (size_t)(b * W_ + half * WC) * L_ : sh;
        char* thi = sm + (isA ? OFF_AHI : OFF_BHI);
        char* tlo = sm + (isA ? OFF_ALO : OFF_BLO);
        float* nrm = isA ? sxx : ssn;
        const int ro  = lane >> 4;
        const int col = (lane & 15) * 4;

        #pragma unroll
        for (int hb = 0; hb < 2; hb++) {
            float4 v[4];
            #pragma unroll
            for (int i = 0; i < 4; i++) {
                const int r = rbase + (hb * 4 + i) * 2 + ro;
                v[i] = *(const float4*)(base + (size_t)r * L_ + col);
            }
            #pragma unroll
            for (int i = 0; i < 4; i++) {
                const int r = rbase + (hb * 4 + i) * 2 + ro;
                __nv_bfloat162 h0 = __float22bfloat162_rn(make_float2(v[i].x, v[i].y));
                __nv_bfloat162 h1 = __float22bfloat162_rn(make_float2(v[i].z, v[i].w));
                uint32_t u0 = *(uint32_t*)&h0, u1 = *(uint32_t*)&h1;
                float hx = __uint_as_float(u0 << 16), hy = __uint_as_float(u0 & 0xFFFF0000u);
                float hz = __uint_as_float(u1 << 16), hw = __uint_as_float(u1 & 0xFFFF0000u);
                __nv_bfloat162 l0 = __float22bfloat162_rn(make_float2(v[i].x - hx, v[i].y - hy));
                __nv_bfloat162 l1 = __float22bfloat162_rn(make_float2(v[i].z - hz, v[i].w - hw));

                const uint32_t o = (uint32_t)(r * PADK + col) * 2;
                *(uint2*)(thi + o) = make_uint2(u0, u1);
                uint32_t w0 = *(uint32_t*)&l0, w1 = *(uint32_t*)&l1;
                *(uint2*)(tlo + o) = make_uint2(w0, w1);

                float nr = fmaf(v[i].x, v[i].x, fmaf(v[i].y, v[i].y,
                           fmaf(v[i].z, v[i].z, v[i].w * v[i].w)));
                nr += __shfl_xor_sync(0xffffffffu, nr, 1);
                nr += __shfl_xor_sync(0xffffffffu, nr, 2);
                nr += __shfl_xor_sync(0xffffffffu, nr, 4);
                nr += __shfl_xor_sync(0xffffffffu, nr, 8);
                if ((lane & 15) == 0) nrm[r] = nr;
            }
        }
    }
    __syncthreads();

    // ---- phase 2: 16 warps, warp tile 32x32, double-buffered fragments ----
    const int mbase = (wid & 3) * 32;
    const int nbase = (wid >> 2) * 32;

    float acc[2][4][4];
    #pragma unroll
    for (int mt = 0; mt < 2; mt++)
        #pragma unroll
        for (int j = 0; j < 4; j++)
            #pragma unroll
            for (int e = 0; e < 4; e++) acc[mt][j][e] = 0.f;

    const uint32_t a_off = (uint32_t)((mbase + (lane & 15)) * PADK + (lane >> 4) * 8) * 2;
    const uint32_t q = lane >> 3;
    const uint32_t b_off = (uint32_t)((nbase + ((q >> 1) << 3) + (lane & 7)) * PADK
                                      + (q & 1) * 8) * 2;

    const uint32_t ahB = smb + OFF_AHI + a_off, alB = smb + OFF_ALO + a_off;
    const uint32_t bhB = smb + OFF_BHI + b_off, blB = smb + OFF_BLO + b_off;

    {
        uint32_t f0[8][4], f1[8][4];
        LOAD_FRAGS(f0, 0);
        LOAD_FRAGS(f1, 32);
        DO_MMAS(f0);
        LOAD_FRAGS(f0, 64);
        DO_MMAS(f1);
        LOAD_FRAGS(f1, 96);
        DO_MMAS(f0);
        DO_MMAS(f1);
    }

    // ---- epilogue: d^2 = xr + sn - 2*dot; min over the warp's 32 rows ----
    {
        const int g = lane >> 2, t = lane & 3;
        const float xr0 = sxx[mbase + g],      xr1 = sxx[mbase + 8 + g];
        const float xr2 = sxx[mbase + 16 + g], xr3 = sxx[mbase + 24 + g];
        #pragma unroll
        for (int j = 0; j < 4; j++) {
            float v0 = fminf(fminf(fmaf(-2.f, acc[0][j][0], xr0), fmaf(-2.f, acc[0][j][2], xr1)),
                             fminf(fmaf(-2.f, acc[1][j][0], xr2), fmaf(-2.f, acc[1][j][2], xr3)));
            float v1 = fminf(fminf(fmaf(-2.f, acc[0][j][1], xr0), fmaf(-2.f, acc[0][j][3], xr1)),
                             fminf(fmaf(-2.f, acc[1][j][1], xr2), fmaf(-2.f, acc[1][j][3], xr3)));
            #pragma unroll
            for (int o = 4; o <= 16; o <<= 1) {
                v0 = fminf(v0, __shfl_xor_sync(0xffffffffu, v0, o));
                v1 = fminf(v1, __shfl_xor_sync(0xffffffffu, v1, o));
            }
            if (lane < 4) {
                int c0 = nbase + j * 8 + t * 2;
                atomicMin(&umin[c0],     __float_as_uint(fmaxf(v0 + ssn[c0], 0.f)));
                atomicMin(&umin[c0 + 1], __float_as_uint(fmaxf(v1 + ssn[c0 + 1], 0.f)));
            }
        }
    }
    __syncthreads();

    // ---- cluster DSMEM merge: rank 1 pushes its half-min into rank 0's smem ----
    if (half == 1 && tid < N_) {
        uint32_t remote;
        asm("mapa.shared::cluster.u32 %0, %1, 0;"
            : "=r"(remote) : "r"(smb + OFF_PEER + tid * 4));
        asm volatile("st.shared::cluster.u32 [%0], %1;"
                     :: "r"(remote), "r"(umin[tid]) : "memory");
    }
    asm volatile("barrier.cluster.arrive.aligned;" ::: "memory");
    asm volatile("barrier.cluster.wait.aligned;" ::: "memory");

    if (half == 0) {
        float v = 0.f;
        if (tid < N_) {
            float d2 = fminf(__uint_as_float(umin[tid]), __uint_as_float(peer[tid]));
            v = sqrtf(fmaxf(d2, 0.f)) * cw[tid];
        }
        #pragma unroll
        for (int o = 16; o; o >>= 1) v += __shfl_xor_sync(0xffffffffu, v, o);
        if (tid < N_ && (tid & 31) == 0) red[tid >> 5] = v;
        __syncthreads();
        if (tid == 0) {
            float s = red[0] + red[1] + red[2] + red[3] + cb[0];
            out[b] = 1.f / (1.f + expf(-s));
        }
    }
}

extern "C" void kernel_launch(void* const* d_in, const int* in_sizes, int n_in,
                              void* d_out, int out_size) {
    const float* x  = (const float*)d_in[0];
    const float* sh = (const float*)d_in[1];
    const float* cw = (const float*)d_in[2];
    const float* cb = (const float*)d_in[3];
    float* out = (float*)d_out;

    cudaFuncSetAttribute(fused_kernel, cudaFuncAttributeMaxDynamicSharedMemorySize, SMEM_TOTAL);
    fused_kernel<<<2 * B_, THREADS, SMEM_TOTAL>>>(x, sh, cw, cb, out);
}